// round 4
// baseline (speedup 1.0000x reference)
#include <cuda_runtime.h>
#include <cuda_bf16.h>
#include <cstdint>

// ExiLU_14147622273111: predicate (x>=1001 || x<=447113) is tautologically
// true, so out = in (identity copy). 512 MiB read + 512 MiB write of fp32.
// R3 measured: 153.9us kernel, DRAM=81.2%, HBM=6641 GB/s. This round:
//  - streaming cache hints (__ldcs/__stcs): working set >> L2, lines are
//    dead after one touch -> evict-first both directions.
//  - 8 x float4 per thread (128 B/thread) for higher per-warp MLP; grid
//    shrinks to 16,384 blocks.

constexpr int THREADS = 256;
constexpr int V4_PER_THREAD = 8;  // 8 x float4 = 128 B per thread

__global__ void __launch_bounds__(THREADS) copy_f4x8_kernel(
    const float4* __restrict__ in, float4* __restrict__ out, long long n4) {
    long long base = (long long)blockIdx.x * (THREADS * V4_PER_THREAD) + threadIdx.x;

    long long last = base + 7LL * THREADS;
    if (last < n4) {
        // Fast path (all blocks for this shape). Front-batch all 8 loads.
        float4 v0 = __ldcs(&in[base + 0LL * THREADS]);
        float4 v1 = __ldcs(&in[base + 1LL * THREADS]);
        float4 v2 = __ldcs(&in[base + 2LL * THREADS]);
        float4 v3 = __ldcs(&in[base + 3LL * THREADS]);
        float4 v4 = __ldcs(&in[base + 4LL * THREADS]);
        float4 v5 = __ldcs(&in[base + 5LL * THREADS]);
        float4 v6 = __ldcs(&in[base + 6LL * THREADS]);
        float4 v7 = __ldcs(&in[base + 7LL * THREADS]);
        __stcs(&out[base + 0LL * THREADS], v0);
        __stcs(&out[base + 1LL * THREADS], v1);
        __stcs(&out[base + 2LL * THREADS], v2);
        __stcs(&out[base + 3LL * THREADS], v3);
        __stcs(&out[base + 4LL * THREADS], v4);
        __stcs(&out[base + 5LL * THREADS], v5);
        __stcs(&out[base + 6LL * THREADS], v6);
        __stcs(&out[base + 7LL * THREADS], v7);
    } else {
        #pragma unroll
        for (int j = 0; j < V4_PER_THREAD; j++) {
            long long i = base + (long long)j * THREADS;
            if (i < n4) out[i] = in[i];
        }
    }
}

__global__ void __launch_bounds__(THREADS) copy_tail_kernel(
    const float* __restrict__ in, float* __restrict__ out,
    long long start, long long n) {
    long long i = start + (long long)blockIdx.x * blockDim.x + threadIdx.x;
    if (i < n) out[i] = in[i];
}

extern "C" void kernel_launch(void* const* d_in, const int* in_sizes, int n_in,
                              void* d_out, int out_size) {
    const float* in = (const float*)d_in[0];
    float* out = (float*)d_out;
    long long n = (long long)in_sizes[0];   // 4096*32768 = 134,217,728

    long long n4 = n / 4;                                             // 33,554,432
    const long long per_block = (long long)THREADS * V4_PER_THREAD;  // 2048 float4
    long long blocks = (n4 + per_block - 1) / per_block;              // 16,384

    copy_f4x8_kernel<<<(unsigned int)blocks, THREADS>>>(
        (const float4*)in, (float4*)out, n4);

    // Tail in elements (never taken for this shape: n % 4 == 0).
    long long tail_start = n4 * 4;
    long long tail = n - tail_start;
    if (tail > 0) {
        long long tblocks = (tail + THREADS - 1) / THREADS;
        copy_tail_kernel<<<(unsigned int)tblocks, THREADS>>>(in, out, tail_start, n);
    }
}